// round 16
// baseline (speedup 1.0000x reference)
#include <cuda_runtime.h>
#include <cstdint>

// Problem dims
#define T_STEPS 512
#define BATCH   64
#define INDIM   256
#define HID     512

// ---------------- f32x2 helpers (FFMA2 only reachable via PTX) ----------------
__device__ __forceinline__ unsigned long long pack2(float x, float y) {
    unsigned long long r;
    asm("mov.b64 %0, {%1,%2};" : "=l"(r) : "f"(x), "f"(y));
    return r;
}
__device__ __forceinline__ void unpack2(unsigned long long v, float& x, float& y) {
    asm("mov.b64 {%0,%1}, %2;" : "=f"(x), "=f"(y) : "l"(v));
}
__device__ __forceinline__ void fma2(unsigned long long& d, unsigned long long a,
                                     unsigned long long b) {
    asm("fma.rn.f32x2 %0, %1, %2, %0;" : "+l"(d) : "l"(a), "l"(b));
}

// ---------------- mbarrier / DSMEM helpers ----------------
__device__ __forceinline__ void mbar_init(unsigned addr, unsigned cnt) {
    asm volatile("mbarrier.init.shared.b64 [%0], %1;" :: "r"(addr), "r"(cnt) : "memory");
}
__device__ __forceinline__ void mbar_expect_tx(unsigned addr, unsigned bytes) {
    asm volatile("mbarrier.arrive.expect_tx.shared.b64 _, [%0], %1;"
                 :: "r"(addr), "r"(bytes) : "memory");
}
__device__ __forceinline__ void mbar_wait(unsigned addr, unsigned parity) {
    asm volatile(
        "{\n\t.reg .pred P;\n"
        "LW_%=:\n\t"
        "mbarrier.try_wait.parity.acquire.cluster.shared::cta.b64 P, [%0], %1, 0x989680;\n\t"
        "@P bra LD_%=;\n\t"
        "bra LW_%=;\n"
        "LD_%=:\n\t}"
        :: "r"(addr), "r"(parity) : "memory");
}
__device__ __forceinline__ unsigned mapa_sh(unsigned addr, unsigned rank) {
    unsigned r;
    asm("mapa.shared::cluster.u32 %0, %1, %2;" : "=r"(r) : "r"(addr), "r"(rank));
    return r;
}
// 1KB bulk DSMEM copy with tx-accounting into the DESTINATION CTA's mbarrier
__device__ __forceinline__ void bulk_dsmem(unsigned dst, unsigned src, unsigned bytes,
                                           unsigned dst_mbar) {
    asm volatile(
        "cp.async.bulk.shared::cluster.shared::cta.mbarrier::complete_tx::bytes "
        "[%0], [%1], %2, [%3];"
        :: "r"(dst), "r"(src), "r"(bytes), "r"(dst_mbar) : "memory");
}
#define CLUSTER_SYNC_ASM() do { \
    asm volatile("barrier.cluster.arrive.aligned;" ::: "memory"); \
    asm volatile("barrier.cluster.wait.aligned;" ::: "memory"); } while (0)

// ---------------- Phase 1: xw = x @ W_ih^T + bias_ih + bias_hh ----------------
__device__ float g_xw[(size_t)T_STEPS * BATCH * HID];   // 64 MB static scratch

#define BM 128
#define BN 128
#define BK 16
#define LDP 132

__global__ void __launch_bounds__(256, 2)
xw_gemm_kernel(const float* __restrict__ x, const float* __restrict__ wih,
               const float* __restrict__ bih, const float* __restrict__ bhh)
{
    __shared__ float As[BK * LDP];
    __shared__ float Bs[BK * LDP];

    const int tid = threadIdx.x;
    const int mb = blockIdx.x * BM;
    const int nb = blockIdx.y * BN;

    const int tx = tid & 15;
    const int ty = tid >> 4;
    const int m0 = ty * 8;
    const int n0 = tx * 8;

    const int lrow = tid >> 2;
    const int lk   = (tid & 3) * 4;

    unsigned long long acc2[4][8];
#pragma unroll
    for (int i = 0; i < 4; ++i)
#pragma unroll
        for (int n = 0; n < 8; ++n) acc2[i][n] = 0ull;

    for (int k0 = 0; k0 < INDIM; k0 += BK) {
#pragma unroll
        for (int h = 0; h < 2; ++h) {
            const int row = lrow + h * 64;
            float4 a = *reinterpret_cast<const float4*>(x + (size_t)(mb + row) * INDIM + k0 + lk);
            As[(lk + 0) * LDP + row] = a.x;
            As[(lk + 1) * LDP + row] = a.y;
            As[(lk + 2) * LDP + row] = a.z;
            As[(lk + 3) * LDP + row] = a.w;
            float4 b = *reinterpret_cast<const float4*>(wih + (size_t)(nb + row) * INDIM + k0 + lk);
            Bs[(lk + 0) * LDP + row] = b.x;
            Bs[(lk + 1) * LDP + row] = b.y;
            Bs[(lk + 2) * LDP + row] = b.z;
            Bs[(lk + 3) * LDP + row] = b.w;
        }
        __syncthreads();

#pragma unroll
        for (int k = 0; k < BK; ++k) {
            const ulonglong2* ap = reinterpret_cast<const ulonglong2*>(As + k * LDP + m0);
            ulonglong2 am0 = ap[0];
            ulonglong2 am1 = ap[1];
            unsigned long long av[4] = {am0.x, am0.y, am1.x, am1.y};
            float4 b0 = *reinterpret_cast<const float4*>(Bs + k * LDP + n0);
            float4 b1 = *reinterpret_cast<const float4*>(Bs + k * LDP + n0 + 4);
            unsigned long long bb[8] = {
                pack2(b0.x, b0.x), pack2(b0.y, b0.y), pack2(b0.z, b0.z), pack2(b0.w, b0.w),
                pack2(b1.x, b1.x), pack2(b1.y, b1.y), pack2(b1.z, b1.z), pack2(b1.w, b1.w)};
#pragma unroll
            for (int i = 0; i < 4; ++i)
#pragma unroll
                for (int n = 0; n < 8; ++n)
                    fma2(acc2[i][n], av[i], bb[n]);
        }
        __syncthreads();
    }

    float bia[8];
#pragma unroll
    for (int n = 0; n < 8; ++n)
        bia[n] = __ldg(bih + nb + n0 + n) + __ldg(bhh + nb + n0 + n);

#pragma unroll
    for (int i = 0; i < 4; ++i) {
        float lo[8], hi[8];
#pragma unroll
        for (int n = 0; n < 8; ++n) unpack2(acc2[i][n], lo[n], hi[n]);
        float* dst0 = g_xw + (size_t)(mb + m0 + 2 * i) * HID + nb + n0;
        float* dst1 = dst0 + HID;
        float4 o;
        o.x = lo[0] + bia[0]; o.y = lo[1] + bia[1]; o.z = lo[2] + bia[2]; o.w = lo[3] + bia[3];
        *reinterpret_cast<float4*>(dst0) = o;
        o.x = lo[4] + bia[4]; o.y = lo[5] + bia[5]; o.z = lo[6] + bia[6]; o.w = lo[7] + bia[7];
        *reinterpret_cast<float4*>(dst0 + 4) = o;
        o.x = hi[0] + bia[0]; o.y = hi[1] + bia[1]; o.z = hi[2] + bia[2]; o.w = hi[3] + bia[3];
        *reinterpret_cast<float4*>(dst1) = o;
        o.x = hi[4] + bia[4]; o.y = hi[5] + bia[5]; o.z = hi[6] + bia[6]; o.w = hi[7] + bia[7];
        *reinterpret_cast<float4*>(dst1 + 4) = o;
    }
}

// ---------------- Phase 2: recurrence (warp-specialized reduce-scatter) ----------------
// 16 clusters x 8 CTAs, 256 threads. CTA rank r owns k-slice AND j-slice [64r,64r+64).
// Warp w (1..7) computes the FULL 1KB partial slice for peer (rank+w)&7 (64 j x 4 b over
// our k-slice, 2 j per lane), stages it, __syncwarp, lane0 fires cp.async.bulk IMMEDIATELY
// -> sends stream out as warps finish (hi-wid-first arbiter favors remote warps), fabric
// flight overlaps remaining warps' FMA work. Warp 0 computes the own slice straight into
// recv. One block sync (overlapped with flight), mbar wait (7x1024B tx), finalize.
// Double buffering + 2-step dependency chain gives WAR ordering (unchanged from R15).

#define CL_SIZE     8
#define RNN_THREADS 256
#define RNN_CTAS    128          // 16 clusters * 8

__global__ void __launch_bounds__(RNN_THREADS, 1) __cluster_dims__(CL_SIZE, 1, 1)
rnn_kernel(const float* __restrict__ whh, float* __restrict__ out)
{
    __shared__ alignas(16) float hcur[4][64];             // 1KB  local h slice
    __shared__ alignas(16) float stage[CL_SIZE][4][64];   // 8KB  per-warp outgoing slices
    __shared__ alignas(16) float recv[2][CL_SIZE][4][64]; // 16KB incoming (dbl buf)
    __shared__ alignas(8)  unsigned long long mbar[2];    // full[0], full[1]

    const int tid  = threadIdx.x;
    const int w    = tid >> 5;       // warp 0..7
    const int lane = tid & 31;
    const int rank = blockIdx.x & (CL_SIZE - 1);
    const int cl   = blockIdx.x >> 3;
    const int b0   = cl * 4;
    const int kb   = rank * 64;      // our k-slice base

    // destination peer for this warp: warp 0 -> own rank; warps 1..7 -> remote
    const int p = (rank + w) & 7;
    // this lane's two j rows within peer p's slice
    const int j1 = p * 64 + lane;
    const int j2 = j1 + 32;

    // W rows for j1, j2 over k in [kb, kb+64): 64 packed u64, register-resident
    unsigned long long w2[64];
    {
        const unsigned long long* r0 =
            reinterpret_cast<const unsigned long long*>(whh + (size_t)j1 * HID + kb);
        const unsigned long long* r1 =
            reinterpret_cast<const unsigned long long*>(whh + (size_t)j2 * HID + kb);
#pragma unroll
        for (int i = 0; i < 32; ++i) { w2[i] = r0[i]; w2[32 + i] = r1[i]; }
    }

    // h(-1) = 0
    (&hcur[0][0])[tid] = 0.f;

    const unsigned mbarL  = (unsigned)__cvta_generic_to_shared(mbar);
    const unsigned recvL  = (unsigned)__cvta_generic_to_shared(&recv[0][0][0][0]);
    const unsigned stageL = (unsigned)__cvta_generic_to_shared(&stage[0][0][0]);

    if (tid == 0) {
        mbar_init(mbarL + 0, 1);
        mbar_init(mbarL + 8, 1);
        mbar_expect_tx(mbarL + 0, 7168);   // step 0: 7 remote slices
        mbar_expect_tx(mbarL + 8, 7168);   // step 1
    }

    // remote addresses for this warp's destination peer
    const unsigned remRecv   = mapa_sh(recvL, (unsigned)p);
    const unsigned remMbar   = mapa_sh(mbarL, (unsigned)p);
    const unsigned mySlotOff = (unsigned)(rank * 1024);   // our slot in peer's recv[wb]
    const unsigned stageSrc  = stageL + (unsigned)(w * 1024);

    // finalize indices: thread tid -> (batch fb, local j fkj) of OWN slice
    const int fb  = tid >> 6;
    const int fkj = tid & 63;
    float xw = g_xw[(size_t)(b0 + fb) * HID + kb + fkj];

    __syncthreads();
    CLUSTER_SYNC_ASM();   // mbarrier inits + expects visible cluster-wide

    int par[2] = {0, 0};

    for (int t = 0; t < T_STEPS; ++t) {
        const int wb = t & 1;

        // ---- GEMV: this warp's slice for peer p (j1, j2 x 4 batches, k in Kr) ----
        unsigned long long acc[8];   // [0..3]=j1 b0..b3, [4..7]=j2 b0..b3
#pragma unroll
        for (int i = 0; i < 8; ++i) acc[i] = 0ull;
        const ulonglong2* p0 = reinterpret_cast<const ulonglong2*>(&hcur[0][0]);
        const ulonglong2* p1 = reinterpret_cast<const ulonglong2*>(&hcur[1][0]);
        const ulonglong2* p2 = reinterpret_cast<const ulonglong2*>(&hcur[2][0]);
        const ulonglong2* p3 = reinterpret_cast<const ulonglong2*>(&hcur[3][0]);
#pragma unroll
        for (int q = 0; q < 16; ++q) {
            ulonglong2 v0 = p0[q], v1 = p1[q], v2 = p2[q], v3 = p3[q];
            unsigned long long wa0 = w2[2 * q], wa1 = w2[2 * q + 1];
            unsigned long long wb0 = w2[32 + 2 * q], wb1 = w2[32 + 2 * q + 1];
            fma2(acc[0], wa0, v0.x); fma2(acc[0], wa1, v0.y);
            fma2(acc[1], wa0, v1.x); fma2(acc[1], wa1, v1.y);
            fma2(acc[2], wa0, v2.x); fma2(acc[2], wa1, v2.y);
            fma2(acc[3], wa0, v3.x); fma2(acc[3], wa1, v3.y);
            fma2(acc[4], wb0, v0.x); fma2(acc[4], wb1, v0.y);
            fma2(acc[5], wb0, v1.x); fma2(acc[5], wb1, v1.y);
            fma2(acc[6], wb0, v2.x); fma2(acc[6], wb1, v2.y);
            fma2(acc[7], wb0, v3.x); fma2(acc[7], wb1, v3.y);
        }

        // ---- stage + immediate per-warp send (no block sync before send) ----
        {
            float x0, y0;
            if (w == 0) {
                // own slice: write straight into local recv[wb][rank]
#pragma unroll
                for (int b = 0; b < 4; ++b) {
                    unpack2(acc[b], x0, y0);     recv[wb][rank][b][lane]      = x0 + y0;
                    unpack2(acc[4 + b], x0, y0); recv[wb][rank][b][lane + 32] = x0 + y0;
                }
            } else {
#pragma unroll
                for (int b = 0; b < 4; ++b) {
                    unpack2(acc[b], x0, y0);     stage[w][b][lane]      = x0 + y0;
                    unpack2(acc[4 + b], x0, y0); stage[w][b][lane + 32] = x0 + y0;
                }
                __syncwarp();
                if (lane == 0) {
                    asm volatile("fence.proxy.async.shared::cta;" ::: "memory");
                    bulk_dsmem(remRecv + (unsigned)(wb * 8192) + mySlotOff,
                               stageSrc, 1024u, remMbar + (unsigned)(wb * 8));
                }
            }
        }

        // prefetch next xw (independent of sync machinery)
        float nxw = xw;
        if (t + 1 < T_STEPS)
            nxw = g_xw[((size_t)(t + 1) * BATCH + b0 + fb) * HID + kb + fkj];

        __syncthreads();   // warp0's recv writes visible; all hcur reads done
                           // (runs concurrently with the in-flight bulks)

        // ---- wait for 7 remote slices of THIS step ----
        mbar_wait(mbarL + wb * 8, par[wb]);
        par[wb] ^= 1;
        if (tid == 0 && t + 2 < T_STEPS) mbar_expect_tx(mbarL + wb * 8, 7168);

        // ---- finalize: sum 8 partials, relu(+xw), write out + hcur ----
        {
            const float* rc = &recv[wb][0][fb][fkj];
            float s = rc[0 * 256] + rc[1 * 256] + rc[2 * 256] + rc[3 * 256]
                    + rc[4 * 256] + rc[5 * 256] + rc[6 * 256] + rc[7 * 256];
            float v = fmaxf(xw + s, 0.f);
            out[((size_t)t * BATCH + b0 + fb) * HID + kb + fkj] = v;
            hcur[fb][fkj] = v;
            if (t == T_STEPS - 1)
                out[(size_t)T_STEPS * BATCH * HID + (size_t)(b0 + fb) * HID + kb + fkj] = v;
        }
        xw = nxw;
        __syncthreads();   // hcur(t) visible before next GEMV
    }
    // keep smem alive until all peers' bulk traffic has drained
    CLUSTER_SYNC_ASM();
}

// ---------------- launch ----------------
extern "C" void kernel_launch(void* const* d_in, const int* in_sizes, int n_in,
                              void* d_out, int out_size)
{
    (void)in_sizes; (void)n_in; (void)out_size;
    const float* x   = (const float*)d_in[0];
    const float* wih = (const float*)d_in[1];
    const float* whh = (const float*)d_in[2];
    const float* bih = (const float*)d_in[3];
    const float* bhh = (const float*)d_in[4];
    float* out = (float*)d_out;

    dim3 g1((T_STEPS * BATCH) / BM, HID / BN);   // (256, 4)
    xw_gemm_kernel<<<g1, 256>>>(x, wih, bih, bhh);

    rnn_kernel<<<RNN_CTAS, RNN_THREADS>>>(whh, out);   // 128 CTAs, 16 clusters
}

// round 17
// speedup vs baseline: 1.2224x; 1.2224x over previous
#include <cuda_runtime.h>
#include <cstdint>

// Problem dims
#define T_STEPS 512
#define BATCH   64
#define INDIM   256
#define HID     512

// ---------------- f32x2 helpers (FFMA2 only reachable via PTX) ----------------
__device__ __forceinline__ unsigned long long pack2(float x, float y) {
    unsigned long long r;
    asm("mov.b64 %0, {%1,%2};" : "=l"(r) : "f"(x), "f"(y));
    return r;
}
__device__ __forceinline__ void unpack2(unsigned long long v, float& x, float& y) {
    asm("mov.b64 {%0,%1}, %2;" : "=f"(x), "=f"(y) : "l"(v));
}
__device__ __forceinline__ void fma2(unsigned long long& d, unsigned long long a,
                                     unsigned long long b) {
    asm("fma.rn.f32x2 %0, %1, %2, %0;" : "+l"(d) : "l"(a), "l"(b));
}

// ---------------- mbarrier / DSMEM helpers ----------------
__device__ __forceinline__ void mbar_init(unsigned addr, unsigned cnt) {
    asm volatile("mbarrier.init.shared.b64 [%0], %1;" :: "r"(addr), "r"(cnt) : "memory");
}
__device__ __forceinline__ void mbar_expect_tx(unsigned addr, unsigned bytes) {
    asm volatile("mbarrier.arrive.expect_tx.shared.b64 _, [%0], %1;"
                 :: "r"(addr), "r"(bytes) : "memory");
}
__device__ __forceinline__ void mbar_wait(unsigned addr, unsigned parity) {
    asm volatile(
        "{\n\t.reg .pred P;\n"
        "LW_%=:\n\t"
        "mbarrier.try_wait.parity.acquire.cluster.shared::cta.b64 P, [%0], %1, 0x989680;\n\t"
        "@P bra LD_%=;\n\t"
        "bra LW_%=;\n"
        "LD_%=:\n\t}"
        :: "r"(addr), "r"(parity) : "memory");
}
__device__ __forceinline__ unsigned mapa_sh(unsigned addr, unsigned rank) {
    unsigned r;
    asm("mapa.shared::cluster.u32 %0, %1, %2;" : "=r"(r) : "r"(addr), "r"(rank));
    return r;
}
// 1KB bulk DSMEM copy with tx-accounting into the DESTINATION CTA's mbarrier
__device__ __forceinline__ void bulk_dsmem(unsigned dst, unsigned src, unsigned bytes,
                                           unsigned dst_mbar) {
    asm volatile(
        "cp.async.bulk.shared::cluster.shared::cta.mbarrier::complete_tx::bytes "
        "[%0], [%1], %2, [%3];"
        :: "r"(dst), "r"(src), "r"(bytes), "r"(dst_mbar) : "memory");
}
#define CLUSTER_SYNC_ASM() do { \
    asm volatile("barrier.cluster.arrive.aligned;" ::: "memory"); \
    asm volatile("barrier.cluster.wait.aligned;" ::: "memory"); } while (0)

// ---------------- Phase 1: xw = x @ W_ih^T + bias_ih + bias_hh ----------------
__device__ float g_xw[(size_t)T_STEPS * BATCH * HID];   // 64 MB static scratch

#define BM 128
#define BN 128
#define BK 16
#define LDP 132

__global__ void __launch_bounds__(256, 2)
xw_gemm_kernel(const float* __restrict__ x, const float* __restrict__ wih,
               const float* __restrict__ bih, const float* __restrict__ bhh)
{
    __shared__ float As[BK * LDP];
    __shared__ float Bs[BK * LDP];

    const int tid = threadIdx.x;
    const int mb = blockIdx.x * BM;
    const int nb = blockIdx.y * BN;

    const int tx = tid & 15;
    const int ty = tid >> 4;
    const int m0 = ty * 8;
    const int n0 = tx * 8;

    const int lrow = tid >> 2;
    const int lk   = (tid & 3) * 4;

    unsigned long long acc2[4][8];
#pragma unroll
    for (int i = 0; i < 4; ++i)
#pragma unroll
        for (int n = 0; n < 8; ++n) acc2[i][n] = 0ull;

    for (int k0 = 0; k0 < INDIM; k0 += BK) {
#pragma unroll
        for (int h = 0; h < 2; ++h) {
            const int row = lrow + h * 64;
            float4 a = *reinterpret_cast<const float4*>(x + (size_t)(mb + row) * INDIM + k0 + lk);
            As[(lk + 0) * LDP + row] = a.x;
            As[(lk + 1) * LDP + row] = a.y;
            As[(lk + 2) * LDP + row] = a.z;
            As[(lk + 3) * LDP + row] = a.w;
            float4 b = *reinterpret_cast<const float4*>(wih + (size_t)(nb + row) * INDIM + k0 + lk);
            Bs[(lk + 0) * LDP + row] = b.x;
            Bs[(lk + 1) * LDP + row] = b.y;
            Bs[(lk + 2) * LDP + row] = b.z;
            Bs[(lk + 3) * LDP + row] = b.w;
        }
        __syncthreads();

#pragma unroll
        for (int k = 0; k < BK; ++k) {
            const ulonglong2* ap = reinterpret_cast<const ulonglong2*>(As + k * LDP + m0);
            ulonglong2 am0 = ap[0];
            ulonglong2 am1 = ap[1];
            unsigned long long av[4] = {am0.x, am0.y, am1.x, am1.y};
            float4 b0 = *reinterpret_cast<const float4*>(Bs + k * LDP + n0);
            float4 b1 = *reinterpret_cast<const float4*>(Bs + k * LDP + n0 + 4);
            unsigned long long bb[8] = {
                pack2(b0.x, b0.x), pack2(b0.y, b0.y), pack2(b0.z, b0.z), pack2(b0.w, b0.w),
                pack2(b1.x, b1.x), pack2(b1.y, b1.y), pack2(b1.z, b1.z), pack2(b1.w, b1.w)};
#pragma unroll
            for (int i = 0; i < 4; ++i)
#pragma unroll
                for (int n = 0; n < 8; ++n)
                    fma2(acc2[i][n], av[i], bb[n]);
        }
        __syncthreads();
    }

    float bia[8];
#pragma unroll
    for (int n = 0; n < 8; ++n)
        bia[n] = __ldg(bih + nb + n0 + n) + __ldg(bhh + nb + n0 + n);

#pragma unroll
    for (int i = 0; i < 4; ++i) {
        float lo[8], hi[8];
#pragma unroll
        for (int n = 0; n < 8; ++n) unpack2(acc2[i][n], lo[n], hi[n]);
        float* dst0 = g_xw + (size_t)(mb + m0 + 2 * i) * HID + nb + n0;
        float* dst1 = dst0 + HID;
        float4 o;
        o.x = lo[0] + bia[0]; o.y = lo[1] + bia[1]; o.z = lo[2] + bia[2]; o.w = lo[3] + bia[3];
        *reinterpret_cast<float4*>(dst0) = o;
        o.x = lo[4] + bia[4]; o.y = lo[5] + bia[5]; o.z = lo[6] + bia[6]; o.w = lo[7] + bia[7];
        *reinterpret_cast<float4*>(dst0 + 4) = o;
        o.x = hi[0] + bia[0]; o.y = hi[1] + bia[1]; o.z = hi[2] + bia[2]; o.w = hi[3] + bia[3];
        *reinterpret_cast<float4*>(dst1) = o;
        o.x = hi[4] + bia[4]; o.y = hi[5] + bia[5]; o.z = hi[6] + bia[6]; o.w = hi[7] + bia[7];
        *reinterpret_cast<float4*>(dst1 + 4) = o;
    }
}

// ---------------- Phase 2: recurrence (two-group pipelined reduce-scatter) ----------------
// 8 clusters x 8 CTAs = 64 CTAs, 256 threads. Cluster = 8 batches as two independent
// recurrence chains: group A (4 batches) and group B (4 batches), interleaved so each
// group's DSMEM flight + cross-CTA skew hides behind the other group's GEMV.
// CTA rank r owns k-slice AND j-slice [64r,64r+64); same w2 registers serve both groups.
// Per group: GEMV over LOCAL hcur -> stage[t&1] -> 7x 1KB cp.async.bulk into peers'
// recv[(t+1)&1], tx-counted (7168B) into full[(t+1)&1]. Stage AND recv double-buffered;
// WAR proven by the full(t+2)-pass causality chain (delivery implies source read done).

#define CL_SIZE     8
#define RNN_THREADS 256
#define RNN_CTAS    64           // 8 clusters * 8

// dynamic smem layout (floats)
#define SM_HCUR0   0                      // [4][64]        256
#define SM_HCUR1   256                    // [4][64]        256
#define SM_STG0    512                    // [2][8][4][64]  4096
#define SM_STG1    4608                   // [2][8][4][64]  4096
#define SM_RCV0    8704                   // [2][8][4][64]  4096
#define SM_RCV1    12800                  // [2][8][4][64]  4096
#define SM_MBAR    16896                  // 4 x u64 (A0,A1,B0,B1)
#define RNN_SMEM_BYTES (16896 * 4 + 32)   // 67616

struct GroupCtx {
    float*   hcur;     // [4*64]
    float*   stg;      // [2*2048]
    unsigned stgL;     // local byte addr of stg
    float*   rcv;      // [2*2048]
    unsigned remRcv;   // peer's rcv byte addr
    int      mbOff;    // 0 for group A, 16 for group B (byte offset of its 2 barriers)
};

__device__ __forceinline__ void group_step(
    int t, int wb, int nb_, int pwait,
    int tid, int rank, int kb, int fb, int fkj, int jl, int pr1, int pr2,
    unsigned peer, const unsigned long long (&w2)[64],
    const GroupCtx& g, unsigned mbarL, unsigned remMbar,
    float& xw, int gb, float* __restrict__ out)
{
    const unsigned mb = mbarL + (unsigned)(g.mbOff + wb * 8);
    if (t > 0) {
        mbar_wait(mb, pwait);
        if (tid == 0 && t + 2 < T_STEPS) mbar_expect_tx(mb, 7168);
    }
    // finalize h(t) for this group
    float s = 0.f;
    if (t > 0) {
        const float* rc = g.rcv + wb * 2048 + fb * 64 + fkj;
        s = rc[0]    + rc[256]  + rc[512]  + rc[768]
          + rc[1024] + rc[1280] + rc[1536] + rc[1792];
    }
    float v = fmaxf(xw + s, 0.f);
    out[((size_t)t * BATCH + gb) * HID + kb + fkj] = v;
    g.hcur[tid] = v;
    if (t == T_STEPS - 1)
        out[(size_t)T_STEPS * BATCH * HID + (size_t)gb * HID + kb + fkj] = v;
    else
        xw = g_xw[((size_t)(t + 1) * BATCH + gb) * HID + kb + fkj];   // prefetch
    __syncthreads();   // hcur(t) visible to all before GEMV

    // GEMV: partials for j1=tid, j2=tid+256 over k in [kb,kb+64), from LOCAL hcur
    unsigned long long acc[8];
#pragma unroll
    for (int i = 0; i < 8; ++i) acc[i] = 0ull;
    {
        const ulonglong2* p0 = reinterpret_cast<const ulonglong2*>(g.hcur);
        const ulonglong2* p1 = reinterpret_cast<const ulonglong2*>(g.hcur + 64);
        const ulonglong2* p2 = reinterpret_cast<const ulonglong2*>(g.hcur + 128);
        const ulonglong2* p3 = reinterpret_cast<const ulonglong2*>(g.hcur + 192);
#pragma unroll
        for (int q = 0; q < 16; ++q) {
            ulonglong2 v0 = p0[q], v1 = p1[q], v2 = p2[q], v3 = p3[q];
            unsigned long long wa0 = w2[2 * q],      wa1 = w2[2 * q + 1];
            unsigned long long wb0 = w2[32 + 2 * q], wb1 = w2[32 + 2 * q + 1];
            fma2(acc[0], wa0, v0.x); fma2(acc[0], wa1, v0.y);
            fma2(acc[1], wa0, v1.x); fma2(acc[1], wa1, v1.y);
            fma2(acc[2], wa0, v2.x); fma2(acc[2], wa1, v2.y);
            fma2(acc[3], wa0, v3.x); fma2(acc[3], wa1, v3.y);
            fma2(acc[4], wb0, v0.x); fma2(acc[4], wb1, v0.y);
            fma2(acc[5], wb0, v1.x); fma2(acc[5], wb1, v1.y);
            fma2(acc[6], wb0, v2.x); fma2(acc[6], wb1, v2.y);
            fma2(acc[7], wb0, v3.x); fma2(acc[7], wb1, v3.y);
        }
    }
    {
        float x0, y0;
        float* sg = g.stg + wb * 2048;
#pragma unroll
        for (int b = 0; b < 4; ++b) {
            unpack2(acc[b], x0, y0);     sg[pr1 * 256 + b * 64 + jl] = x0 + y0;
            unpack2(acc[4 + b], x0, y0); sg[pr2 * 256 + b * 64 + jl] = x0 + y0;
        }
    }
    __syncthreads();   // staging complete; everyone done reading hcur

    if (t + 1 < T_STEPS) {
        // 7 remote 1KB bulks, tx into peer's full[nb_] of this group
        if (tid < 7) {
            asm volatile("fence.proxy.async.shared::cta;" ::: "memory");
            bulk_dsmem(g.remRcv + (unsigned)(nb_ * 8192 + rank * 1024),
                       g.stgL + (unsigned)(wb * 8192) + peer * 1024u, 1024u,
                       remMbar + (unsigned)(g.mbOff + nb_ * 8));
        }
        // own slice: local copy (ordered by later __syncthreads before next read)
        g.rcv[nb_ * 2048 + rank * 256 + tid] = g.stg[wb * 2048 + rank * 256 + tid];
    }
}

__global__ void __launch_bounds__(RNN_THREADS, 1) __cluster_dims__(CL_SIZE, 1, 1)
rnn_kernel(const float* __restrict__ whh, float* __restrict__ out)
{
    extern __shared__ float smf[];

    const int tid  = threadIdx.x;
    const int rank = blockIdx.x & (CL_SIZE - 1);
    const int cl   = blockIdx.x >> 3;
    const int b0   = cl * 8;         // 8 batches per cluster (two groups of 4)
    const int kb   = rank * 64;
    const int jl   = tid & 63;
    const int pr1  = tid >> 6;       // peer owning j1 = tid
    const int pr2  = 4 + pr1;        // peer owning j2 = tid + 256
    const int fb   = tid >> 6;
    const int fkj  = tid & 63;

    // W rows j1=tid, j2=tid+256 over k in [kb,kb+64): 64 packed u64 (128 regs)
    unsigned long long w2[64];
    {
        const unsigned long long* r0 =
            reinterpret_cast<const unsigned long long*>(whh + (size_t)tid * HID + kb);
        const unsigned long long* r1 =
            reinterpret_cast<const unsigned long long*>(whh + (size_t)(tid + 256) * HID + kb);
#pragma unroll
        for (int i = 0; i < 32; ++i) { w2[i] = r0[i]; w2[32 + i] = r1[i]; }
    }

    const unsigned mbarL = (unsigned)__cvta_generic_to_shared(smf + SM_MBAR);
    if (tid == 0) {
#pragma unroll
        for (int i = 0; i < 4; ++i) {
            mbar_init(mbarL + i * 8, 1);
            mbar_expect_tx(mbarL + i * 8, 7168);   // first fill of each buffer
        }
    }

    // bulk issuers: tid 0..6 -> peer skipping own rank
    const unsigned peer    = (unsigned)(tid + (tid >= rank ? 1 : 0)) & 7u;
    const unsigned remMbar = mapa_sh(mbarL, peer);

    GroupCtx gA, gB;
    gA.hcur = smf + SM_HCUR0;  gA.stg = smf + SM_STG0;  gA.rcv = smf + SM_RCV0;
    gB.hcur = smf + SM_HCUR1;  gB.stg = smf + SM_STG1;  gB.rcv = smf + SM_RCV1;
    gA.stgL = (unsigned)__cvta_generic_to_shared(gA.stg);
    gB.stgL = (unsigned)__cvta_generic_to_shared(gB.stg);
    gA.remRcv = mapa_sh((unsigned)__cvta_generic_to_shared(gA.rcv), peer);
    gB.remRcv = mapa_sh((unsigned)__cvta_generic_to_shared(gB.rcv), peer);
    gA.mbOff = 0;
    gB.mbOff = 16;

    const int gbA = b0 + fb;
    const int gbB = b0 + 4 + fb;
    float xwA = g_xw[(size_t)gbA * HID + kb + fkj];
    float xwB = g_xw[(size_t)gbB * HID + kb + fkj];

    __syncthreads();
    CLUSTER_SYNC_ASM();   // barrier inits + expects visible cluster-wide

    for (int t = 0; t < T_STEPS; ++t) {
        const int wb  = t & 1;
        const int nb_ = wb ^ 1;
        // parity for the n-th wait on buffer wb (first wait: t=1 for buf1, t=2 for buf0)
        const int pwait = ((t >> 1) & 1) ^ ((t & 1) ^ 1);

        // Group A: wait/finalize/GEMV/send — its flight hides behind B's phase
        group_step(t, wb, nb_, pwait, tid, rank, kb, fb, fkj, jl, pr1, pr2,
                   peer, w2, gA, mbarL, remMbar, xwA, gbA, out);
        // Group B: flight hides behind next iteration's A phase
        group_step(t, wb, nb_, pwait, tid, rank, kb, fb, fkj, jl, pr1, pr2,
                   peer, w2, gB, mbarL, remMbar, xwB, gbB, out);
    }
    // keep smem alive until all peers' bulk traffic has drained
    CLUSTER_SYNC_ASM();
}

// ---------------- launch ----------------
extern "C" void kernel_launch(void* const* d_in, const int* in_sizes, int n_in,
                              void* d_out, int out_size)
{
    (void)in_sizes; (void)n_in; (void)out_size;
    const float* x   = (const float*)d_in[0];
    const float* wih = (const float*)d_in[1];
    const float* whh = (const float*)d_in[2];
    const float* bih = (const float*)d_in[3];
    const float* bhh = (const float*)d_in[4];
    float* out = (float*)d_out;

    dim3 g1((T_STEPS * BATCH) / BM, HID / BN);   // (256, 4)
    xw_gemm_kernel<<<g1, 256>>>(x, wih, bih, bhh);

    // dynamic smem > 48KB requires opt-in (host-side attribute set; capture-safe)
    cudaFuncSetAttribute(rnn_kernel, cudaFuncAttributeMaxDynamicSharedMemorySize,
                         RNN_SMEM_BYTES);
    rnn_kernel<<<RNN_CTAS, RNN_THREADS, RNN_SMEM_BYTES>>>(whh, out);   // 64 CTAs, 8 clusters
}